// round 2
// baseline (speedup 1.0000x reference)
#include <cuda_runtime.h>
#include <math.h>

// Problem constants (from reference setup_inputs)
#define NB 4
#define NE 16
#define NP 320000          // 400*800
#define NC 20
#define CK 19              // kept classes (exclude IGNORE=0)
#define T_TILE 4096
#define RPT 16             // pixels per thread (256 threads * 16 = 4096)
#define NTILES 79          // ceil(320000/4096)

__device__ float g_sums[NB][NC][NE];
__device__ float g_counts[NB][NC];
__device__ float g_hinge[NB][NC];

__global__ void k_zero() {
    int tid = threadIdx.x;
    float* s = &g_sums[0][0][0];
    for (int j = tid; j < NB * NC * NE; j += blockDim.x) s[j] = 0.f;
    float* c = &g_counts[0][0];
    for (int j = tid; j < NB * NC; j += blockDim.x) c[j] = 0.f;
    float* h = &g_hinge[0][0];
    for (int j = tid; j < NB * NC; j += blockDim.x) h[j] = 0.f;
}

// Pass 1: per-class sums over each embedding dim + per-class counts.
// Column-private shared accumulation: thread tid only ever touches
// s_acc[c*256 + tid] -> no races, no bank conflicts, no atomics in the hot loop.
__global__ __launch_bounds__(256) void k_accum(const float* __restrict__ emb,
                                               const int* __restrict__ tgt) {
    __shared__ float s_acc[NC * 256];
    const int tid = threadIdx.x;
    const int n = blockIdx.y;
    const int p0 = blockIdx.x * T_TILE;
    const int base = p0 + tid * RPT;
    const bool full = (base + RPT <= NP);

    // Precompute slots (label*256 + tid), -1 if out of range.
    int slot[RPT];
    const int* tl = tgt + (size_t)n * NP;
    if (full) {
        const int4* t4 = (const int4*)(tl + base);
#pragma unroll
        for (int rv = 0; rv < 4; rv++) {
            int4 v = t4[rv];
            slot[rv * 4 + 0] = v.x * 256 + tid;
            slot[rv * 4 + 1] = v.y * 256 + tid;
            slot[rv * 4 + 2] = v.z * 256 + tid;
            slot[rv * 4 + 3] = v.w * 256 + tid;
        }
    } else {
#pragma unroll
        for (int r = 0; r < RPT; r++) {
            int p = base + r;
            slot[r] = (p < NP) ? (tl[p] * 256 + tid) : -1;
        }
    }

    const int w = tid >> 5;
    const int lane = tid & 31;

    for (int pass = 0; pass < NE + 1; ++pass) {
#pragma unroll
        for (int c = 0; c < NC; c++) s_acc[c * 256 + tid] = 0.f;

        if (pass < NE) {
            const float* plane = emb + ((size_t)(n * NE + pass)) * NP;
            if (full) {
                const float4* p4 = (const float4*)(plane + base);
#pragma unroll
                for (int rv = 0; rv < 4; rv++) {
                    float4 x = p4[rv];
                    s_acc[slot[rv * 4 + 0]] += x.x;
                    s_acc[slot[rv * 4 + 1]] += x.y;
                    s_acc[slot[rv * 4 + 2]] += x.z;
                    s_acc[slot[rv * 4 + 3]] += x.w;
                }
            } else {
#pragma unroll
                for (int r = 0; r < RPT; r++) {
                    int s = slot[r];
                    if (s >= 0) s_acc[s] += plane[base + r];
                }
            }
        } else {
#pragma unroll
            for (int r = 0; r < RPT; r++) {
                int s = slot[r];
                if (s >= 0) s_acc[s] += 1.0f;
            }
        }
        __syncthreads();

        // Reduce 256 columns per class; each class owned by one warp.
        for (int c = w; c < NC; c += 8) {
            float v = 0.f;
#pragma unroll
            for (int k = 0; k < 8; k++) v += s_acc[c * 256 + lane + k * 32];
            v += __shfl_down_sync(0xffffffffu, v, 16);
            v += __shfl_down_sync(0xffffffffu, v, 8);
            v += __shfl_down_sync(0xffffffffu, v, 4);
            v += __shfl_down_sync(0xffffffffu, v, 2);
            v += __shfl_down_sync(0xffffffffu, v, 1);
            if (lane == 0) {
                if (pass < NE) atomicAdd(&g_sums[n][c][pass], v);
                else           atomicAdd(&g_counts[n][c], v);
            }
        }
        __syncthreads();
    }
}

// Pass 2: per-pixel pull hinge accumulated per class.
__global__ __launch_bounds__(256) void k_var(const float* __restrict__ emb,
                                             const int* __restrict__ tgt) {
    __shared__ float s_meanT[NE * NC];   // [e][c] layout -> conflict-free gathers
    __shared__ float s_h[NC * 256];
    const int tid = threadIdx.x;
    const int n = blockIdx.y;
    const int p0 = blockIdx.x * T_TILE;

    // FIX: NC*NE = 320 > blockDim (256) -> must stride, not guard.
    for (int i = tid; i < NC * NE; i += 256) {
        int c = i >> 4;
        int e = i & 15;
        s_meanT[e * NC + c] = g_sums[n][c][e] / g_counts[n][c];
    }
#pragma unroll
    for (int c = 0; c < NC; c++) s_h[c * 256 + tid] = 0.f;
    __syncthreads();

    const int* tl = tgt + (size_t)n * NP;
    const float* eb = emb + (size_t)n * NE * NP;

#pragma unroll 4
    for (int r = 0; r < RPT; r++) {
        int p = p0 + r * 256 + tid;
        if (p < NP) {
            int lab = tl[p];
            if (lab != 0) {
                float d2 = 0.f;
#pragma unroll
                for (int e = 0; e < NE; e++) {
                    float x = eb[(size_t)e * NP + p];
                    float m = s_meanT[e * NC + lab];
                    float df = x - m;
                    d2 = fmaf(df, df, d2);
                }
                float d = (d2 > 0.f) ? sqrtf(d2) : 0.f;
                float h = fmaxf(d - 0.5f, 0.f);
                s_h[lab * 256 + tid] += h * h;
            }
        }
    }
    __syncthreads();

    const int w = tid >> 5;
    const int lane = tid & 31;
    for (int c = 1 + w; c < NC; c += 8) {
        float v = 0.f;
#pragma unroll
        for (int k = 0; k < 8; k++) v += s_h[c * 256 + lane + k * 32];
        v += __shfl_down_sync(0xffffffffu, v, 16);
        v += __shfl_down_sync(0xffffffffu, v, 8);
        v += __shfl_down_sync(0xffffffffu, v, 4);
        v += __shfl_down_sync(0xffffffffu, v, 2);
        v += __shfl_down_sync(0xffffffffu, v, 1);
        if (lane == 0) atomicAdd(&g_hinge[n][c], v);
    }
}

// Finalize: variance term + pairwise push term + regularizer -> scalar.
__global__ __launch_bounds__(512) void k_final(float* __restrict__ out) {
    __shared__ float s_mean[NB][NC][NE];
    __shared__ float s_cnt[NB][NC];
    __shared__ float s_t[NB * 3];
    const int tid = threadIdx.x;

    for (int i = tid; i < NB * NC; i += blockDim.x)
        s_cnt[i / NC][i % NC] = (&g_counts[0][0])[i];
    for (int i = tid; i < NB * NC * NE; i += blockDim.x) {
        int n = i / (NC * NE);
        int rem = i % (NC * NE);
        int c = rem >> 4;
        int e = rem & 15;
        s_mean[n][c][e] = (&g_sums[0][0][0])[i] / (&g_counts[0][0])[n * NC + c];
    }
    if (tid < NB * 3) s_t[tid] = 0.f;
    __syncthreads();

    // variance term: sum_c hinge[c]/count[c]
    for (int i = tid; i < NB * CK; i += blockDim.x) {
        int n = i / CK;
        int c = 1 + i % CK;
        atomicAdd(&s_t[n * 3 + 0], g_hinge[n][c] / s_cnt[n][c]);
    }
    // distance term: all ordered pairs a != b among kept classes
    for (int i = tid; i < NB * CK * CK; i += blockDim.x) {
        int n = i / (CK * CK);
        int r = i % (CK * CK);
        int a = 1 + r / CK;
        int b = 1 + r % CK;
        if (a != b) {
            float d2 = 0.f;
#pragma unroll
            for (int e = 0; e < NE; e++) {
                float df = s_mean[n][a][e] - s_mean[n][b][e];
                d2 = fmaf(df, df, d2);
            }
            float d = (d2 > 0.f) ? sqrtf(d2) : 0.f;
            float h = fmaxf(3.0f - d, 0.f);   // 2*DELTA_DIST = 3.0
            atomicAdd(&s_t[n * 3 + 1], h * h);
        }
    }
    // regularizer: sum_c ||mean_c||
    for (int i = tid; i < NB * CK; i += blockDim.x) {
        int n = i / CK;
        int c = 1 + i % CK;
        float d2 = 0.f;
#pragma unroll
        for (int e = 0; e < NE; e++) {
            float m = s_mean[n][c][e];
            d2 = fmaf(m, m, d2);
        }
        float d = (d2 > 0.f) ? sqrtf(d2) : 0.f;
        atomicAdd(&s_t[n * 3 + 2], d);
    }
    __syncthreads();

    if (tid == 0) {
        float tot = 0.f;
        for (int n = 0; n < NB; n++) {
            tot += s_t[n * 3 + 0] / (float)CK
                 + s_t[n * 3 + 1] / (float)(CK * (CK - 1))
                 + 0.001f * (s_t[n * 3 + 2] / (float)CK);
        }
        out[0] = tot * 0.25f;   // mean over batch
    }
}

extern "C" void kernel_launch(void* const* d_in, const int* in_sizes, int n_in,
                              void* d_out, int out_size) {
    const float* emb = (const float*)d_in[0];
    const int* tgt = (const int*)d_in[1];
    float* out = (float*)d_out;

    k_zero<<<1, 512>>>();
    dim3 grid(NTILES, NB);
    k_accum<<<grid, 256>>>(emb, tgt);
    k_var<<<grid, 256>>>(emb, tgt);
    k_final<<<1, 512>>>(out);
}

// round 3
// speedup vs baseline: 1.2895x; 1.2895x over previous
#include <cuda_runtime.h>
#include <math.h>

// Problem constants (from reference setup_inputs)
#define NB 4
#define NE 16
#define NP 320000          // 400*800
#define NC 20
#define CK 19              // kept classes (exclude IGNORE=0)
#define T_TILE 4096
#define RPT 16             // pixels per thread (256 threads * 16 = 4096)
#define NTILES 79          // ceil(320000/4096)

// Zero-initialized at module load; k_final re-zeroes them after reading,
// so every launch (and every graph replay) starts from zeros.
__device__ float g_sums[NB][NC][NE];
__device__ float g_counts[NB][NC];
__device__ float g_hinge[NB][NC];

// Pass 1: per-class sums over each embedding dim + per-class counts.
// Column-private shared accumulation: thread tid only ever touches
// s_acc[c*256 + tid] -> no races, no bank conflicts, no atomics in the hot loop.
__global__ __launch_bounds__(256) void k_accum(const float* __restrict__ emb,
                                               const int* __restrict__ tgt) {
    __shared__ float s_acc[NC * 256];
    const int tid = threadIdx.x;
    const int n = blockIdx.y;
    const int p0 = blockIdx.x * T_TILE;
    const int base = p0 + tid * RPT;
    const bool full = (base + RPT <= NP);

    // Precompute slots (label*256 + tid), -1 if out of range.
    int slot[RPT];
    const int* tl = tgt + (size_t)n * NP;
    if (full) {
        const int4* t4 = (const int4*)(tl + base);
#pragma unroll
        for (int rv = 0; rv < 4; rv++) {
            int4 v = t4[rv];
            slot[rv * 4 + 0] = v.x * 256 + tid;
            slot[rv * 4 + 1] = v.y * 256 + tid;
            slot[rv * 4 + 2] = v.z * 256 + tid;
            slot[rv * 4 + 3] = v.w * 256 + tid;
        }
    } else {
#pragma unroll
        for (int r = 0; r < RPT; r++) {
            int p = base + r;
            slot[r] = (p < NP) ? (tl[p] * 256 + tid) : -1;
        }
    }

    const int w = tid >> 5;
    const int lane = tid & 31;

    for (int pass = 0; pass < NE + 1; ++pass) {
#pragma unroll
        for (int c = 0; c < NC; c++) s_acc[c * 256 + tid] = 0.f;

        if (pass < NE) {
            const float* plane = emb + ((size_t)(n * NE + pass)) * NP;
            if (full) {
                const float4* p4 = (const float4*)(plane + base);
#pragma unroll
                for (int rv = 0; rv < 4; rv++) {
                    float4 x = p4[rv];
                    s_acc[slot[rv * 4 + 0]] += x.x;
                    s_acc[slot[rv * 4 + 1]] += x.y;
                    s_acc[slot[rv * 4 + 2]] += x.z;
                    s_acc[slot[rv * 4 + 3]] += x.w;
                }
            } else {
#pragma unroll
                for (int r = 0; r < RPT; r++) {
                    int s = slot[r];
                    if (s >= 0) s_acc[s] += plane[base + r];
                }
            }
        } else {
#pragma unroll
            for (int r = 0; r < RPT; r++) {
                int s = slot[r];
                if (s >= 0) s_acc[s] += 1.0f;
            }
        }
        __syncthreads();

        // Reduce 256 columns per class; each class owned by one warp.
        for (int c = w; c < NC; c += 8) {
            float v = 0.f;
#pragma unroll
            for (int k = 0; k < 8; k++) v += s_acc[c * 256 + lane + k * 32];
            v += __shfl_down_sync(0xffffffffu, v, 16);
            v += __shfl_down_sync(0xffffffffu, v, 8);
            v += __shfl_down_sync(0xffffffffu, v, 4);
            v += __shfl_down_sync(0xffffffffu, v, 2);
            v += __shfl_down_sync(0xffffffffu, v, 1);
            if (lane == 0) {
                if (pass < NE) atomicAdd(&g_sums[n][c][pass], v);
                else           atomicAdd(&g_counts[n][c], v);
            }
        }
        __syncthreads();
    }
}

// Pass 2: per-pixel pull hinge accumulated per class.
__global__ __launch_bounds__(256) void k_var(const float* __restrict__ emb,
                                             const int* __restrict__ tgt) {
    __shared__ float s_meanT[NE * NC];   // [e][c] layout -> conflict-free gathers
    __shared__ float s_h[NC * 256];
    const int tid = threadIdx.x;
    const int n = blockIdx.y;
    const int p0 = blockIdx.x * T_TILE;

    for (int i = tid; i < NC * NE; i += 256) {
        int c = i >> 4;
        int e = i & 15;
        s_meanT[e * NC + c] = g_sums[n][c][e] / g_counts[n][c];
    }
#pragma unroll
    for (int c = 0; c < NC; c++) s_h[c * 256 + tid] = 0.f;
    __syncthreads();

    const int* tl = tgt + (size_t)n * NP;
    const float* eb = emb + (size_t)n * NE * NP;

#pragma unroll 4
    for (int r = 0; r < RPT; r++) {
        int p = p0 + r * 256 + tid;
        if (p < NP) {
            int lab = tl[p];
            if (lab != 0) {
                float d2 = 0.f;
#pragma unroll
                for (int e = 0; e < NE; e++) {
                    float x = eb[(size_t)e * NP + p];
                    float m = s_meanT[e * NC + lab];
                    float df = x - m;
                    d2 = fmaf(df, df, d2);
                }
                float d = (d2 > 0.f) ? sqrtf(d2) : 0.f;
                float h = fmaxf(d - 0.5f, 0.f);
                s_h[lab * 256 + tid] += h * h;
            }
        }
    }
    __syncthreads();

    const int w = tid >> 5;
    const int lane = tid & 31;
    for (int c = 1 + w; c < NC; c += 8) {
        float v = 0.f;
#pragma unroll
        for (int k = 0; k < 8; k++) v += s_h[c * 256 + lane + k * 32];
        v += __shfl_down_sync(0xffffffffu, v, 16);
        v += __shfl_down_sync(0xffffffffu, v, 8);
        v += __shfl_down_sync(0xffffffffu, v, 4);
        v += __shfl_down_sync(0xffffffffu, v, 2);
        v += __shfl_down_sync(0xffffffffu, v, 1);
        if (lane == 0) atomicAdd(&g_hinge[n][c], v);
    }
}

// Finalize: variance + push + regularizer -> scalar. NO shared atomics:
// register accumulation + shuffle-tree block reduction. Also re-zeroes
// the global accumulators for the next launch.
__global__ __launch_bounds__(512) void k_final(float* __restrict__ out) {
    __shared__ float s_mean[NB][NC][NE];
    __shared__ float s_cnt[NB][NC];
    __shared__ float s_red[16 * 3];
    const int tid = threadIdx.x;

    for (int i = tid; i < NB * NC; i += 512)
        (&s_cnt[0][0])[i] = (&g_counts[0][0])[i];
    for (int i = tid; i < NB * NC * NE; i += 512) {
        int n = i / (NC * NE);
        int c = (i % (NC * NE)) >> 4;
        (&s_mean[0][0][0])[i] = (&g_sums[0][0][0])[i] / (&g_counts[0][0])[n * NC + c];
    }
    __syncthreads();

    float acc_v = 0.f, acc_d = 0.f, acc_r = 0.f;

    // variance term items: NB*CK  (divisor 1/CK is n-independent -> fold batch)
    for (int i = tid; i < NB * CK; i += 512) {
        int n = i / CK;
        int c = 1 + i % CK;
        acc_v += g_hinge[n][c] / s_cnt[n][c];
    }
    // distance term items: NB*CK*CK ordered pairs, skip diagonal
    for (int i = tid; i < NB * CK * CK; i += 512) {
        int n = i / (CK * CK);
        int r = i % (CK * CK);
        int a = 1 + r / CK;
        int b = 1 + r % CK;
        if (a != b) {
            float d2 = 0.f;
#pragma unroll
            for (int e = 0; e < NE; e++) {
                float df = s_mean[n][a][e] - s_mean[n][b][e];
                d2 = fmaf(df, df, d2);
            }
            float d = (d2 > 0.f) ? sqrtf(d2) : 0.f;
            float h = fmaxf(3.0f - d, 0.f);   // 2*DELTA_DIST
            acc_d += h * h;
        }
    }
    // regularizer items: NB*CK
    for (int i = tid; i < NB * CK; i += 512) {
        int n = i / CK;
        int c = 1 + i % CK;
        float d2 = 0.f;
#pragma unroll
        for (int e = 0; e < NE; e++) {
            float m = s_mean[n][c][e];
            d2 = fmaf(m, m, d2);
        }
        acc_r += (d2 > 0.f) ? sqrtf(d2) : 0.f;
    }

    // warp reduce 3 scalars
#pragma unroll
    for (int o = 16; o > 0; o >>= 1) {
        acc_v += __shfl_down_sync(0xffffffffu, acc_v, o);
        acc_d += __shfl_down_sync(0xffffffffu, acc_d, o);
        acc_r += __shfl_down_sync(0xffffffffu, acc_r, o);
    }
    const int w = tid >> 5;
    const int lane = tid & 31;
    if (lane == 0) {
        s_red[w * 3 + 0] = acc_v;
        s_red[w * 3 + 1] = acc_d;
        s_red[w * 3 + 2] = acc_r;
    }
    __syncthreads();

    // Re-zero global accumulators for the next launch (all reads done).
    {
        float* s = &g_sums[0][0][0];
        for (int j = tid; j < NB * NC * NE; j += 512) s[j] = 0.f;
        float* c = &g_counts[0][0];
        for (int j = tid; j < NB * NC; j += 512) c[j] = 0.f;
        float* h = &g_hinge[0][0];
        for (int j = tid; j < NB * NC; j += 512) h[j] = 0.f;
    }

    if (tid == 0) {
        float v = 0.f, d = 0.f, r = 0.f;
#pragma unroll
        for (int k = 0; k < 16; k++) {
            v += s_red[k * 3 + 0];
            d += s_red[k * 3 + 1];
            r += s_red[k * 3 + 2];
        }
        float tot = v / (float)CK
                  + d / (float)(CK * (CK - 1))
                  + 0.001f * (r / (float)CK);
        out[0] = tot * 0.25f;   // mean over batch
    }
}

extern "C" void kernel_launch(void* const* d_in, const int* in_sizes, int n_in,
                              void* d_out, int out_size) {
    const float* emb = (const float*)d_in[0];
    const int* tgt = (const int*)d_in[1];
    float* out = (float*)d_out;

    dim3 grid(NTILES, NB);
    k_accum<<<grid, 256>>>(emb, tgt);
    k_var<<<grid, 256>>>(emb, tgt);
    k_final<<<1, 512>>>(out);
}

// round 4
// speedup vs baseline: 1.3833x; 1.0727x over previous
#include <cuda_runtime.h>
#include <math.h>

// Problem constants (from reference setup_inputs)
#define NB 4
#define NE 16
#define NP 320000          // 400*800
#define NC 20
#define CK 19              // kept classes (exclude IGNORE=0)

// k_accum tiling: 79 tiles x 4 batches x 5 pass-chunks
#define T_TILE 4096
#define RPT 16
#define NTILES 79          // ceil(320000/4096)
#define EC 4               // e-planes per chunk
#define NCHUNK 5           // 4 e-chunks + 1 count chunk

// k_var tiling: higher block count for latency hiding
#define TV_TILE 2048
#define RPTV 8
#define NTILES_V 157       // ceil(320000/2048)

// Zero-initialized at module load; k_final re-zeroes them after reading,
// so every launch (and every graph replay) starts from zeros.
__device__ float g_sums[NB][NC][NE];
__device__ float g_counts[NB][NC];
__device__ float g_hinge[NB][NC];

// Pass 1: per-class sums (4 e-planes per block via blockIdx.z) + counts.
// Column-private shared accumulation: thread tid only ever touches
// s_acc[c*256 + tid] -> race-free, bank-conflict-free, no atomics in hot loop.
__global__ __launch_bounds__(256) void k_accum(const float* __restrict__ emb,
                                               const int* __restrict__ tgt) {
    __shared__ float s_acc[NC * 256];
    const int tid = threadIdx.x;
    const int n = blockIdx.y;
    const int chunk = blockIdx.z;
    const int p0 = blockIdx.x * T_TILE;
    const int base = p0 + tid * RPT;
    const bool full = (base + RPT <= NP);

    // Precompute slots (label*256 + tid), -1 if out of range.
    int slot[RPT];
    const int* tl = tgt + (size_t)n * NP;
    if (full) {
        const int4* t4 = (const int4*)(tl + base);
#pragma unroll
        for (int rv = 0; rv < 4; rv++) {
            int4 v = t4[rv];
            slot[rv * 4 + 0] = v.x * 256 + tid;
            slot[rv * 4 + 1] = v.y * 256 + tid;
            slot[rv * 4 + 2] = v.z * 256 + tid;
            slot[rv * 4 + 3] = v.w * 256 + tid;
        }
    } else {
#pragma unroll
        for (int r = 0; r < RPT; r++) {
            int p = base + r;
            slot[r] = (p < NP) ? (tl[p] * 256 + tid) : -1;
        }
    }

    const int w = tid >> 5;
    const int lane = tid & 31;

    if (chunk < 4) {
#pragma unroll
        for (int pe = 0; pe < EC; pe++) {
            const int e = chunk * EC + pe;
#pragma unroll
            for (int c = 0; c < NC; c++) s_acc[c * 256 + tid] = 0.f;

            const float* plane = emb + ((size_t)(n * NE + e)) * NP;
            if (full) {
                const float4* p4 = (const float4*)(plane + base);
#pragma unroll
                for (int rv = 0; rv < 4; rv++) {
                    float4 x = p4[rv];
                    s_acc[slot[rv * 4 + 0]] += x.x;
                    s_acc[slot[rv * 4 + 1]] += x.y;
                    s_acc[slot[rv * 4 + 2]] += x.z;
                    s_acc[slot[rv * 4 + 3]] += x.w;
                }
            } else {
#pragma unroll
                for (int r = 0; r < RPT; r++) {
                    int s = slot[r];
                    if (s >= 0) s_acc[s] += plane[base + r];
                }
            }
            __syncthreads();

            // Reduce 256 columns per class; each class owned by one warp.
            for (int c = w; c < NC; c += 8) {
                float v = 0.f;
#pragma unroll
                for (int k = 0; k < 8; k++) v += s_acc[c * 256 + lane + k * 32];
                v += __shfl_down_sync(0xffffffffu, v, 16);
                v += __shfl_down_sync(0xffffffffu, v, 8);
                v += __shfl_down_sync(0xffffffffu, v, 4);
                v += __shfl_down_sync(0xffffffffu, v, 2);
                v += __shfl_down_sync(0xffffffffu, v, 1);
                if (lane == 0) atomicAdd(&g_sums[n][c][e], v);
            }
            __syncthreads();
        }
    } else {
        // count chunk
#pragma unroll
        for (int c = 0; c < NC; c++) s_acc[c * 256 + tid] = 0.f;
#pragma unroll
        for (int r = 0; r < RPT; r++) {
            int s = slot[r];
            if (s >= 0) s_acc[s] += 1.0f;
        }
        __syncthreads();
        for (int c = w; c < NC; c += 8) {
            float v = 0.f;
#pragma unroll
            for (int k = 0; k < 8; k++) v += s_acc[c * 256 + lane + k * 32];
            v += __shfl_down_sync(0xffffffffu, v, 16);
            v += __shfl_down_sync(0xffffffffu, v, 8);
            v += __shfl_down_sync(0xffffffffu, v, 4);
            v += __shfl_down_sync(0xffffffffu, v, 2);
            v += __shfl_down_sync(0xffffffffu, v, 1);
            if (lane == 0) atomicAdd(&g_counts[n][c], v);
        }
    }
}

// Pass 2: per-pixel pull hinge accumulated per class.
__global__ __launch_bounds__(256) void k_var(const float* __restrict__ emb,
                                             const int* __restrict__ tgt) {
    __shared__ float s_meanT[NE * NC];   // [e][c] layout -> conflict-free gathers
    __shared__ float s_h[NC * 256];
    const int tid = threadIdx.x;
    const int n = blockIdx.y;
    const int p0 = blockIdx.x * TV_TILE;

    for (int i = tid; i < NC * NE; i += 256) {
        int c = i >> 4;
        int e = i & 15;
        s_meanT[e * NC + c] = g_sums[n][c][e] / g_counts[n][c];
    }
#pragma unroll
    for (int c = 0; c < NC; c++) s_h[c * 256 + tid] = 0.f;
    __syncthreads();

    const int* tl = tgt + (size_t)n * NP;
    const float* eb = emb + (size_t)n * NE * NP;

#pragma unroll
    for (int r = 0; r < RPTV; r++) {
        int p = p0 + r * 256 + tid;
        if (p < NP) {
            int lab = tl[p];
            if (lab != 0) {
                float d2 = 0.f;
#pragma unroll
                for (int e = 0; e < NE; e++) {
                    float x = eb[(size_t)e * NP + p];
                    float m = s_meanT[e * NC + lab];
                    float df = x - m;
                    d2 = fmaf(df, df, d2);
                }
                float d = (d2 > 0.f) ? sqrtf(d2) : 0.f;
                float h = fmaxf(d - 0.5f, 0.f);
                s_h[lab * 256 + tid] += h * h;
            }
        }
    }
    __syncthreads();

    const int w = tid >> 5;
    const int lane = tid & 31;
    for (int c = 1 + w; c < NC; c += 8) {
        float v = 0.f;
#pragma unroll
        for (int k = 0; k < 8; k++) v += s_h[c * 256 + lane + k * 32];
        v += __shfl_down_sync(0xffffffffu, v, 16);
        v += __shfl_down_sync(0xffffffffu, v, 8);
        v += __shfl_down_sync(0xffffffffu, v, 4);
        v += __shfl_down_sync(0xffffffffu, v, 2);
        v += __shfl_down_sync(0xffffffffu, v, 1);
        if (lane == 0) atomicAdd(&g_hinge[n][c], v);
    }
}

// Finalize: variance + push + regularizer -> scalar. Register accumulation
// + shuffle-tree block reduction; re-zeroes global accumulators afterward.
__global__ __launch_bounds__(512) void k_final(float* __restrict__ out) {
    __shared__ float s_mean[NB][NC][NE];
    __shared__ float s_cnt[NB][NC];
    __shared__ float s_red[16 * 3];
    const int tid = threadIdx.x;

    for (int i = tid; i < NB * NC; i += 512)
        (&s_cnt[0][0])[i] = (&g_counts[0][0])[i];
    for (int i = tid; i < NB * NC * NE; i += 512) {
        int n = i / (NC * NE);
        int c = (i % (NC * NE)) >> 4;
        (&s_mean[0][0][0])[i] = (&g_sums[0][0][0])[i] / (&g_counts[0][0])[n * NC + c];
    }
    __syncthreads();

    float acc_v = 0.f, acc_d = 0.f, acc_r = 0.f;

    for (int i = tid; i < NB * CK; i += 512) {
        int n = i / CK;
        int c = 1 + i % CK;
        acc_v += g_hinge[n][c] / s_cnt[n][c];
    }
    for (int i = tid; i < NB * CK * CK; i += 512) {
        int n = i / (CK * CK);
        int r = i % (CK * CK);
        int a = 1 + r / CK;
        int b = 1 + r % CK;
        if (a != b) {
            float d2 = 0.f;
#pragma unroll
            for (int e = 0; e < NE; e++) {
                float df = s_mean[n][a][e] - s_mean[n][b][e];
                d2 = fmaf(df, df, d2);
            }
            float d = (d2 > 0.f) ? sqrtf(d2) : 0.f;
            float h = fmaxf(3.0f - d, 0.f);   // 2*DELTA_DIST
            acc_d += h * h;
        }
    }
    for (int i = tid; i < NB * CK; i += 512) {
        int n = i / CK;
        int c = 1 + i % CK;
        float d2 = 0.f;
#pragma unroll
        for (int e = 0; e < NE; e++) {
            float m = s_mean[n][c][e];
            d2 = fmaf(m, m, d2);
        }
        acc_r += (d2 > 0.f) ? sqrtf(d2) : 0.f;
    }

#pragma unroll
    for (int o = 16; o > 0; o >>= 1) {
        acc_v += __shfl_down_sync(0xffffffffu, acc_v, o);
        acc_d += __shfl_down_sync(0xffffffffu, acc_d, o);
        acc_r += __shfl_down_sync(0xffffffffu, acc_r, o);
    }
    const int w = tid >> 5;
    const int lane = tid & 31;
    if (lane == 0) {
        s_red[w * 3 + 0] = acc_v;
        s_red[w * 3 + 1] = acc_d;
        s_red[w * 3 + 2] = acc_r;
    }
    __syncthreads();

    // Re-zero global accumulators for the next launch (all reads done).
    {
        float* s = &g_sums[0][0][0];
        for (int j = tid; j < NB * NC * NE; j += 512) s[j] = 0.f;
        float* c = &g_counts[0][0];
        for (int j = tid; j < NB * NC; j += 512) c[j] = 0.f;
        float* h = &g_hinge[0][0];
        for (int j = tid; j < NB * NC; j += 512) h[j] = 0.f;
    }

    if (tid == 0) {
        float v = 0.f, d = 0.f, r = 0.f;
#pragma unroll
        for (int k = 0; k < 16; k++) {
            v += s_red[k * 3 + 0];
            d += s_red[k * 3 + 1];
            r += s_red[k * 3 + 2];
        }
        float tot = v / (float)CK
                  + d / (float)(CK * (CK - 1))
                  + 0.001f * (r / (float)CK);
        out[0] = tot * 0.25f;   // mean over batch
    }
}

extern "C" void kernel_launch(void* const* d_in, const int* in_sizes, int n_in,
                              void* d_out, int out_size) {
    const float* emb = (const float*)d_in[0];
    const int* tgt = (const int*)d_in[1];
    float* out = (float*)d_out;

    dim3 grid_a(NTILES, NB, NCHUNK);
    k_accum<<<grid_a, 256>>>(emb, tgt);
    dim3 grid_v(NTILES_V, NB);
    k_var<<<grid_v, 256>>>(emb, tgt);
    k_final<<<1, 512>>>(out);
}

// round 5
// speedup vs baseline: 2.1324x; 1.5416x over previous
#include <cuda_runtime.h>
#include <math.h>

// Problem constants (from reference setup_inputs)
#define NB 4
#define NE 16
#define NP 320000          // 400*800
#define NQ 80000           // NP/4 pixel-quads
#define NC 20
#define CK 19              // kept classes (exclude IGNORE=0)

// k_accum: 40 tiles x 4 batches x 5 chunks (4 e-quads + 1 count), 128 thr
#define AT_TILE 8192
#define AQPT 16            // quads per thread = 8192/4/128
#define ATILES 40          // ceil(320000/8192)

// k_var: 256 thr, 2 quads per thread
#define VQPT 2
#define VTILES 157         // ceil(80000/512)

__device__ float g_sums[NB][NC][NE];
__device__ float g_counts[NB][NC];
__device__ float g_hinge[NB][NC];

// Pass 1: per-class sums, 4 e-planes at a time with a float4 shared
// accumulator (component = e-dim). Column-private: thread tid only touches
// s4[c*128+tid] -> race-free, bank-conflict-free, no atomics in hot loop.
__global__ __launch_bounds__(128) void k_accum(const float* __restrict__ emb,
                                               const int* __restrict__ tgt) {
    __shared__ float4 s4[NC * 128];    // 40 KB
    const int tid = threadIdx.x;
    const int n = blockIdx.y;
    const int chunk = blockIdx.z;
    const int p0 = blockIdx.x * AT_TILE;
    const int w = tid >> 5;
    const int lane = tid & 31;
    const int* tl = tgt + (size_t)n * NP;

    if (chunk < 4) {
        const int e0 = chunk * 4;
        const float* pl0 = emb + ((size_t)(n * NE + e0 + 0)) * NP;
        const float* pl1 = emb + ((size_t)(n * NE + e0 + 1)) * NP;
        const float* pl2 = emb + ((size_t)(n * NE + e0 + 2)) * NP;
        const float* pl3 = emb + ((size_t)(n * NE + e0 + 3)) * NP;

#pragma unroll
        for (int c = 0; c < NC; c++)
            s4[c * 128 + tid] = make_float4(0.f, 0.f, 0.f, 0.f);
        // no sync needed: each thread touches only its own column until reduce

#pragma unroll 4
        for (int q = 0; q < AQPT; q++) {
            int p = p0 + (q * 128 + tid) * 4;
            if (p < NP) {
                int4 lb = *(const int4*)(tl + p);
                float4 a = *(const float4*)(pl0 + p);
                float4 b = *(const float4*)(pl1 + p);
                float4 c4 = *(const float4*)(pl2 + p);
                float4 d4 = *(const float4*)(pl3 + p);
                {   // pixel 0
                    float4* s = &s4[lb.x * 128 + tid];
                    float4 t = *s;
                    t.x += a.x; t.y += b.x; t.z += c4.x; t.w += d4.x;
                    *s = t;
                }
                {   // pixel 1
                    float4* s = &s4[lb.y * 128 + tid];
                    float4 t = *s;
                    t.x += a.y; t.y += b.y; t.z += c4.y; t.w += d4.y;
                    *s = t;
                }
                {   // pixel 2
                    float4* s = &s4[lb.z * 128 + tid];
                    float4 t = *s;
                    t.x += a.z; t.y += b.z; t.z += c4.z; t.w += d4.z;
                    *s = t;
                }
                {   // pixel 3
                    float4* s = &s4[lb.w * 128 + tid];
                    float4 t = *s;
                    t.x += a.w; t.y += b.w; t.z += c4.w; t.w += d4.w;
                    *s = t;
                }
            }
        }
        __syncthreads();

        // Reduce: warp w handles classes w, w+4, ...
        for (int c = w; c < NC; c += 4) {
            float4 v0 = s4[c * 128 + lane];
            float4 v1 = s4[c * 128 + lane + 32];
            float4 v2 = s4[c * 128 + lane + 64];
            float4 v3 = s4[c * 128 + lane + 96];
            float4 v;
            v.x = (v0.x + v1.x) + (v2.x + v3.x);
            v.y = (v0.y + v1.y) + (v2.y + v3.y);
            v.z = (v0.z + v1.z) + (v2.z + v3.z);
            v.w = (v0.w + v1.w) + (v2.w + v3.w);
#pragma unroll
            for (int o = 16; o > 0; o >>= 1) {
                v.x += __shfl_down_sync(0xffffffffu, v.x, o);
                v.y += __shfl_down_sync(0xffffffffu, v.y, o);
                v.z += __shfl_down_sync(0xffffffffu, v.z, o);
                v.w += __shfl_down_sync(0xffffffffu, v.w, o);
            }
            if (lane == 0) {
                atomicAdd(&g_sums[n][c][e0 + 0], v.x);
                atomicAdd(&g_sums[n][c][e0 + 1], v.y);
                atomicAdd(&g_sums[n][c][e0 + 2], v.z);
                atomicAdd(&g_sums[n][c][e0 + 3], v.w);
            }
        }
    } else {
        // count chunk: scalar columns in the same shared buffer
        float* sc = (float*)s4;
#pragma unroll
        for (int c = 0; c < NC; c++) sc[c * 128 + tid] = 0.f;

#pragma unroll 4
        for (int q = 0; q < AQPT; q++) {
            int p = p0 + (q * 128 + tid) * 4;
            if (p < NP) {
                int4 lb = *(const int4*)(tl + p);
                sc[lb.x * 128 + tid] += 1.f;
                sc[lb.y * 128 + tid] += 1.f;
                sc[lb.z * 128 + tid] += 1.f;
                sc[lb.w * 128 + tid] += 1.f;
            }
        }
        __syncthreads();

        for (int c = w; c < NC; c += 4) {
            float v = (sc[c * 128 + lane] + sc[c * 128 + lane + 32]) +
                      (sc[c * 128 + lane + 64] + sc[c * 128 + lane + 96]);
#pragma unroll
            for (int o = 16; o > 0; o >>= 1)
                v += __shfl_down_sync(0xffffffffu, v, o);
            if (lane == 0) atomicAdd(&g_counts[n][c], v);
        }
    }
}

// Pass 2: per-pixel pull hinge, pixel-quad vectorized global loads.
__global__ __launch_bounds__(256) void k_var(const float* __restrict__ emb,
                                             const int* __restrict__ tgt) {
    __shared__ float s_meanT[NE * NC];   // [e][c]: conflict-free gathers
    __shared__ float s_h[NC * 256];
    const int tid = threadIdx.x;
    const int n = blockIdx.y;
    const int q0 = blockIdx.x * (256 * VQPT);

    for (int i = tid; i < NC * NE; i += 256) {
        int c = i >> 4;
        int e = i & 15;
        s_meanT[e * NC + c] = g_sums[n][c][e] / g_counts[n][c];
    }
#pragma unroll
    for (int c = 0; c < NC; c++) s_h[c * 256 + tid] = 0.f;
    __syncthreads();

    const int* tl = tgt + (size_t)n * NP;
    const float* eb = emb + (size_t)n * NE * NP;

#pragma unroll
    for (int qi = 0; qi < VQPT; qi++) {
        int q = q0 + qi * 256 + tid;
        if (q < NQ) {
            int p = q * 4;
            int4 lb = *(const int4*)(tl + p);
            float dx = 0.f, dy = 0.f, dz = 0.f, dw = 0.f;
#pragma unroll
            for (int e = 0; e < NE; e++) {
                float4 v = *(const float4*)(eb + (size_t)e * NP + p);
                const float* mrow = &s_meanT[e * NC];
                float t;
                t = v.x - mrow[lb.x]; dx = fmaf(t, t, dx);
                t = v.y - mrow[lb.y]; dy = fmaf(t, t, dy);
                t = v.z - mrow[lb.z]; dz = fmaf(t, t, dz);
                t = v.w - mrow[lb.w]; dw = fmaf(t, t, dw);
            }
            if (lb.x != 0) {
                float d = (dx > 0.f) ? sqrtf(dx) : 0.f;
                float h = fmaxf(d - 0.5f, 0.f);
                s_h[lb.x * 256 + tid] += h * h;
            }
            if (lb.y != 0) {
                float d = (dy > 0.f) ? sqrtf(dy) : 0.f;
                float h = fmaxf(d - 0.5f, 0.f);
                s_h[lb.y * 256 + tid] += h * h;
            }
            if (lb.z != 0) {
                float d = (dz > 0.f) ? sqrtf(dz) : 0.f;
                float h = fmaxf(d - 0.5f, 0.f);
                s_h[lb.z * 256 + tid] += h * h;
            }
            if (lb.w != 0) {
                float d = (dw > 0.f) ? sqrtf(dw) : 0.f;
                float h = fmaxf(d - 0.5f, 0.f);
                s_h[lb.w * 256 + tid] += h * h;
            }
        }
    }
    __syncthreads();

    const int w = tid >> 5;
    const int lane = tid & 31;
    for (int c = 1 + w; c < NC; c += 8) {
        float v = 0.f;
#pragma unroll
        for (int k = 0; k < 8; k++) v += s_h[c * 256 + lane + k * 32];
#pragma unroll
        for (int o = 16; o > 0; o >>= 1)
            v += __shfl_down_sync(0xffffffffu, v, o);
        if (lane == 0) atomicAdd(&g_hinge[n][c], v);
    }
}

// Finalize: variance + push + regularizer -> scalar. Register accumulation
// + shuffle-tree block reduction; re-zeroes global accumulators afterward.
__global__ __launch_bounds__(512) void k_final(float* __restrict__ out) {
    __shared__ float s_mean[NB][NC][NE];
    __shared__ float s_cnt[NB][NC];
    __shared__ float s_red[16 * 3];
    const int tid = threadIdx.x;

    for (int i = tid; i < NB * NC; i += 512)
        (&s_cnt[0][0])[i] = (&g_counts[0][0])[i];
    for (int i = tid; i < NB * NC * NE; i += 512) {
        int n = i / (NC * NE);
        int c = (i % (NC * NE)) >> 4;
        (&s_mean[0][0][0])[i] = (&g_sums[0][0][0])[i] / (&g_counts[0][0])[n * NC + c];
    }
    __syncthreads();

    float acc_v = 0.f, acc_d = 0.f, acc_r = 0.f;

    for (int i = tid; i < NB * CK; i += 512) {
        int n = i / CK;
        int c = 1 + i % CK;
        acc_v += g_hinge[n][c] / s_cnt[n][c];
    }
    for (int i = tid; i < NB * CK * CK; i += 512) {
        int n = i / (CK * CK);
        int r = i % (CK * CK);
        int a = 1 + r / CK;
        int b = 1 + r % CK;
        if (a != b) {
            float d2 = 0.f;
#pragma unroll
            for (int e = 0; e < NE; e++) {
                float df = s_mean[n][a][e] - s_mean[n][b][e];
                d2 = fmaf(df, df, d2);
            }
            float d = (d2 > 0.f) ? sqrtf(d2) : 0.f;
            float h = fmaxf(3.0f - d, 0.f);   // 2*DELTA_DIST
            acc_d += h * h;
        }
    }
    for (int i = tid; i < NB * CK; i += 512) {
        int n = i / CK;
        int c = 1 + i % CK;
        float d2 = 0.f;
#pragma unroll
        for (int e = 0; e < NE; e++) {
            float m = s_mean[n][c][e];
            d2 = fmaf(m, m, d2);
        }
        acc_r += (d2 > 0.f) ? sqrtf(d2) : 0.f;
    }

#pragma unroll
    for (int o = 16; o > 0; o >>= 1) {
        acc_v += __shfl_down_sync(0xffffffffu, acc_v, o);
        acc_d += __shfl_down_sync(0xffffffffu, acc_d, o);
        acc_r += __shfl_down_sync(0xffffffffu, acc_r, o);
    }
    const int w = tid >> 5;
    const int lane = tid & 31;
    if (lane == 0) {
        s_red[w * 3 + 0] = acc_v;
        s_red[w * 3 + 1] = acc_d;
        s_red[w * 3 + 2] = acc_r;
    }
    __syncthreads();

    // Re-zero global accumulators for the next launch (all reads done).
    {
        float* s = &g_sums[0][0][0];
        for (int j = tid; j < NB * NC * NE; j += 512) s[j] = 0.f;
        float* c = &g_counts[0][0];
        for (int j = tid; j < NB * NC; j += 512) c[j] = 0.f;
        float* h = &g_hinge[0][0];
        for (int j = tid; j < NB * NC; j += 512) h[j] = 0.f;
    }

    if (tid == 0) {
        float v = 0.f, d = 0.f, r = 0.f;
#pragma unroll
        for (int k = 0; k < 16; k++) {
            v += s_red[k * 3 + 0];
            d += s_red[k * 3 + 1];
            r += s_red[k * 3 + 2];
        }
        float tot = v / (float)CK
                  + d / (float)(CK * (CK - 1))
                  + 0.001f * (r / (float)CK);
        out[0] = tot * 0.25f;   // mean over batch
    }
}

extern "C" void kernel_launch(void* const* d_in, const int* in_sizes, int n_in,
                              void* d_out, int out_size) {
    const float* emb = (const float*)d_in[0];
    const int* tgt = (const int*)d_in[1];
    float* out = (float*)d_out;

    dim3 grid_a(ATILES, NB, 5);
    k_accum<<<grid_a, 128>>>(emb, tgt);
    dim3 grid_v(VTILES, NB);
    k_var<<<grid_v, 256>>>(emb, tgt);
    k_final<<<1, 512>>>(out);
}